// round 11
// baseline (speedup 1.0000x reference)
#include <cuda_runtime.h>
#include <cuda_bf16.h>

// FrequencyFilter: gather 256 ch -> K-tap gauss_low (sigma=2000 samp) low-pass
// -> filt = x - low + mean(low) -> K-tap gauss_high (sigma=100 samp) smoothing.
// K = 12001, pad = (K-1)//2 = 6000 (parameterized at runtime).
//
//  * low computed at stride-64 nodes from 8-sample presums (S8) with aggregated
//    8-tap avg weights (8-phase x 2-half polyphase), cubic interpolated.
//  * output computed at stride-8 nodes (8-phase polyphase, 16-node tiles to
//    halve L2 traffic, phases split over 4 blocks), cubic interpolated.
//  * mean(low) via prefix sums of gauss_low + channel-summed S8.
//  * conv threads own 4 channels (LDG.128 rows), packed fma.rn.f32x2 math,
//    per-phase weight tables enabling paired 128-bit weight loads.

#define T_LEN   100000
#define C_SEL   256
#define C_IN    512

// ---- low-pass stage (S8) ----
#define S8_N     12500            // 8-sample presum blocks
#define S8_PADL  768
#define S8_PADR  832
#define S8_ROWS  (S8_PADL + S8_N + S8_PADR)   // 14100
#define NLN      1568             // low nodes, node j at t = 64*(j-1)
#define NPHASE   16               // 8 phases x 2 tap-range halves

// ---- filt buffer (zero padded in time) ----
#define F_PADL   640
#define F_PADR   880
#define F_ROWS   (F_PADL + T_LEN + F_PADR)    // 101520

// ---- high-pass output nodes ----
#define NYN      12560            // node i at t = 8*i - 8 (12503 used + tile slack)
#define NYPART   4                // k6 phase split
#define WH_STRIDE 144             // high weight table row stride (c in [-64,80))

typedef unsigned long long ull;

// ------------------- packed f32x2 helpers (sm_103a) -------------------
__device__ __forceinline__ ull pack2f(float v) {
    ull r; asm("mov.b64 %0, {%1, %1};" : "=l"(r) : "f"(v)); return r;
}
__device__ __forceinline__ void ffma2(ull& d, ull a, ull b) {
    asm("fma.rn.f32x2 %0, %1, %2, %0;" : "+l"(d) : "l"(a), "l"(b));
}

// ------------------- device scratch (static, no allocation) -------------------
__device__ __align__(16) float g_P[12002];                 // prefix of gauss_low
__device__ __align__(16) ull  g_WL[8 * 256];               // low weights  [r][v], {w,w} packed
__device__ __align__(16) ull  g_WHL[8 * WH_STRIDE];        // high weights [rr][c+64], {w,w} packed
__device__ float g_mean_num;                               // numerator of mean(low)
__device__ __align__(16) float g_S8[(size_t)S8_ROWS * 256];            // 14.4 MB
__device__ __align__(16) float g_LNp[(size_t)NPHASE * NLN * 256];      // 25.7 MB
__device__ __align__(16) float g_LN[NLN * 256];                        // 1.6 MB
__device__ __align__(16) float g_FILT[(size_t)F_ROWS * 256];           // 104 MB
__device__ __align__(16) float g_YNp[(size_t)NYPART * NYN * 256];      // 51.4 MB

// ------------------- K2: prefix of gauss_low + packed weight tables + init -------------------
__global__ void k2_prep(const float* __restrict__ gl, const float* __restrict__ gh,
                        int K, int pad) {
    __shared__ float tot[256];
    const int tid = threadIdx.x;
    const int base = tid * 48;
    float s = 0.f;
    for (int i = 0; i < 48; i++) { int k = base + i; if (k < K) s += gl[k]; }
    tot[tid] = s;
    __syncthreads();
    if (tid == 0) {
        float run = 0.f;
        for (int i = 0; i < 256; i++) { float v = tot[i]; tot[i] = run; run += v; }
        g_P[K] = run;
        g_mean_num = 0.f;
    }
    __syncthreads();
    float run = tot[tid];
    for (int i = 0; i < 48; i++) {
        int k = base + i;
        if (k < K) { g_P[k] = run; run += gl[k]; }
    }
    __syncthreads();
    // low weight table: g_WL[r*256+v] = avg of 8 gauss_low taps at block QQ = 8v+r-2,
    // taps k = 8*(QQ-750)+pad+{0..7}; zero outside QQ in [0,1500] or v >= 200.
    for (int q = tid; q < 8 * 256; q += 256) {
        int r = q >> 8, v = q & 255;
        float val = 0.f;
        int QQ = 8 * v + r - 2;
        if (v < 200 && QQ >= 0 && QQ <= 1500) {
            int lo = 8 * (QQ - 750) + pad;
            int hi = min(lo + 8, K);
            lo = max(lo, 0);
            if (hi > lo) val = 0.125f * (g_P[hi] - g_P[lo]);
        }
        g_WL[q] = pack2f(val);
    }
    // high weight table: g_WHL[rr*WH_STRIDE + c + 64] = gauss_high[pad + 8 + 8c + rr],
    // c in [-64, 80); taps beyond the stored kernel window are zero.
    for (int q = tid; q < 8 * WH_STRIDE; q += 256) {
        int rr = q / WH_STRIDE, c = (q % WH_STRIDE) - 64;
        float val = 0.f;
        if (c >= -56 && c <= 56) {
            int k = pad + 8 + 8 * c + rr;
            if (k >= 0 && k < K) val = gh[k];
        }
        g_WHL[q] = pack2f(val);
    }
}

// ------------------- K3: 8-sample presums (zero-padded rows) -------------------
__global__ void k3_presum(const float* __restrict__ x, const int* __restrict__ sel) {
    const int nb = blockIdx.x;               // [0, S8_ROWS)
    const int c = threadIdx.x;
    const int n = nb - S8_PADL;
    float v = 0.f;
    if (n >= 0 && n < S8_N) {
        const int ci = __ldg(&sel[c]);
        const float* xp = x + (size_t)(8 * n) * C_IN + ci;
        float a0 = xp[0] + xp[C_IN];
        float a1 = xp[2 * C_IN] + xp[3 * C_IN];
        float a2 = xp[4 * C_IN] + xp[5 * C_IN];
        float a3 = xp[6 * C_IN] + xp[7 * C_IN];
        v = (a0 + a1) + (a2 + a3);
    }
    g_S8[(size_t)nb * 256 + c] = v;
}

// ------------------- K3b: mean(low) numerator -------------------
__global__ void k3b_mean(int K, int pad) {
    const int n = blockIdx.x * 256 + threadIdx.x;
    float part = 0.f;
    if (n < S8_N) {
        const float4* row = (const float4*)(g_S8 + (size_t)(n + S8_PADL) * 256);
        float s = 0.f;
        #pragma unroll 8
        for (int i = 0; i < 64; i++) { float4 v = row[i]; s += (v.x + v.y) + (v.z + v.w); }
        float cf = 0.f;
        #pragma unroll
        for (int i = 0; i < 8; i++) {
            int m = 8 * n + i;
            cf += g_P[min(m + pad + 1, K)] - g_P[max(0, m + pad + 1 - T_LEN)];
        }
        part = s * cf * 0.125f;
    }
    #pragma unroll
    for (int o = 16; o > 0; o >>= 1) part += __shfl_down_sync(0xffffffffu, part, o);
    __shared__ float sw[8];
    if ((threadIdx.x & 31) == 0) sw[threadIdx.x >> 5] = part;
    __syncthreads();
    if (threadIdx.x == 0) {
        float s = 0.f;
        #pragma unroll
        for (int i = 0; i < 8; i++) s += sw[i];
        atomicAdd(&g_mean_num, s);
    }
}

// ------------------- K4: low-pass node values (4-channel threads, FFMA2) -------------------
// grid (49, 16): 4 node-groups per block; r = y&7 (phase), h = y>>3 (tap half).
__global__ void __launch_bounds__(256) k4_lownodes() {
    const int tid = threadIdx.x;
    const int grp = blockIdx.x * 4 + (tid >> 6);    // node group [0,196)
    const int cp4 = tid & 63;                       // 4-channel index
    const int r   = blockIdx.y & 7;
    const int h   = blockIdx.y >> 3;
    const int j0  = grp * 8;

    ulonglong2 acc[8];
    #pragma unroll
    for (int i = 0; i < 8; i++) { acc[i].x = 0ULL; acc[i].y = 0ULL; }

    const int rowoff = r + 8 * j0 + 8;              // padded row at v=0
    const ulonglong2* p = (const ulonglong2*)g_S8 + (size_t)rowoff * 64 + cp4;
    const ulonglong2* wp = (const ulonglong2*)(g_WL + r * 256);

    ull wprev[7];
    if (h == 0) {
        #pragma unroll
        for (int t = 0; t < 7; t++) wprev[t] = 0ULL;   // weights for v<0 are zero
    } else {
        #pragma unroll
        for (int t = 0; t < 7; t++) wprev[t] = g_WL[r * 256 + 89 + t];
    }
    const int vb_lo = h ? 12 : 0;
    const int vb_hi = h ? 25 : 12;
    p += vb_lo * 4096;
    for (int vb = vb_lo; vb < vb_hi; vb++) {
        ull w8[8];
        {
            const int pb = vb * 4;                  // ulonglong2 pair base = v0/2
            ulonglong2 q0 = wp[pb], q1 = wp[pb + 1], q2 = wp[pb + 2], q3 = wp[pb + 3];
            w8[0] = q0.x; w8[1] = q0.y; w8[2] = q1.x; w8[3] = q1.y;
            w8[4] = q2.x; w8[5] = q2.y; w8[6] = q3.x; w8[7] = q3.y;
        }
        #pragma unroll
        for (int u = 0; u < 8; u++) {
            ulonglong2 sv = p[u * 512];
            #pragma unroll
            for (int ii = 0; ii < 8; ii++) {
                int e = u - ii;
                ull w = (e >= 0) ? w8[e] : wprev[7 + e];
                ffma2(acc[ii].x, sv.x, w);
                ffma2(acc[ii].y, sv.y, w);
            }
        }
        #pragma unroll
        for (int t = 0; t < 7; t++) wprev[t] = w8[t + 1];
        p += 4096;
    }
    ulonglong2* out = (ulonglong2*)(g_LNp + (size_t)blockIdx.y * NLN * 256);
    #pragma unroll
    for (int ii = 0; ii < 8; ii++)
        out[(size_t)(j0 + ii) * 64 + cp4] = acc[ii];
}

// ------------------- K4c: combine 16 phase partials -------------------
__global__ void k4c_combine() {
    const size_t i = (size_t)blockIdx.x * 256 + threadIdx.x;   // NLN*256
    const size_t S = (size_t)NLN * 256;
    float s = 0.f;
    #pragma unroll
    for (int p = 0; p < NPHASE; p++) s += g_LNp[(size_t)p * S + i];
    g_LN[i] = s;
}

// ------------------- K5: materialize filt = x - interp(low) + mean (zero padded) -------------------
__global__ void k5_filt(const float* __restrict__ x, const int* __restrict__ sel) {
    const int row = blockIdx.x;            // [0, F_ROWS)
    const int m = row - F_PADL;
    const int c = threadIdx.x;
    float v = 0.f;
    if (m >= 0 && m < T_LEN) {
        const int j0 = m >> 6;
        const float s = (float)(m & 63) * (1.f / 64.f);
        const float sm1 = s + 1.f, s1 = s - 1.f, s2 = s - 2.f;
        const float wm1 = -s * s1 * s2 * (1.f / 6.f);
        const float w0  = sm1 * s1 * s2 * 0.5f;
        const float w1  = -sm1 * s * s2 * 0.5f;
        const float w2  = sm1 * s * s1 * (1.f / 6.f);
        const float* ln = g_LN + (size_t)j0 * 256 + c;
        const float lowI = wm1 * ln[0] + w0 * ln[256] + w1 * ln[512] + w2 * ln[768];
        const float mean = g_mean_num * (1.f / 25600000.f);
        v = x[(size_t)m * C_IN + __ldg(&sel[c])] - lowI + mean;
    }
    g_FILT[(size_t)row * 256 + c] = v;
}

// ------------------- K6: high-pass conv, 16-node tiles (4-channel threads, FFMA2) ----
// Node i at t = 8i - 8. Y[i] = sum_k wh[k] * filt[t + k - pad].
// 16 nodes per thread (halves L2 read traffic vs 8). Tap offsets c in [-55,55]
// effective (table zero-padded to [-64,80)). Phases rr split 4-way over grid.y.
__global__ void __launch_bounds__(256, 2) k6_conv() {
    const int tid = threadIdx.x;
    const int grp = blockIdx.x * 4 + (tid >> 6);    // node group [0,784)
    const int cp4 = tid & 63;                       // 4-channel index
    const int i0  = grp * 16;
    const int rbase = blockIdx.y * 2;               // phase pair {0,2,4,6}

    ulonglong2 acc[16];
    #pragma unroll
    for (int i = 0; i < 16; i++) { acc[i].x = 0ULL; acc[i].y = 0ULL; }

    for (int rr2 = 0; rr2 < 2; rr2++) {
        const int rr = rbase + rr2;
        const ulonglong2* p = (const ulonglong2*)g_FILT
                            + (size_t)(8 * i0 + rr + F_PADL) * 64 + cp4
                            - 56 * 8 * 64;           // position at cb = -56
        const ulonglong2* wp = (const ulonglong2*)(g_WHL + rr * WH_STRIDE);
        ull wprev[15];
        #pragma unroll
        for (int t = 0; t < 15; t++) wprev[t] = 0ULL;   // c = -71..-57: zero
        for (int cb = -56; cb <= 64; cb += 8) {
            ull w8[8];
            {
                const int pb = (cb + 64) >> 1;       // ulonglong2 pair base
                ulonglong2 q0 = wp[pb], q1 = wp[pb + 1], q2 = wp[pb + 2], q3 = wp[pb + 3];
                w8[0] = q0.x; w8[1] = q0.y; w8[2] = q1.x; w8[3] = q1.y;
                w8[4] = q2.x; w8[5] = q2.y; w8[6] = q3.x; w8[7] = q3.y;
            }
            #pragma unroll
            for (int u = 0; u < 8; u++) {
                ulonglong2 fv = p[u * 512];
                #pragma unroll
                for (int ii = 0; ii < 16; ii++) {
                    int e = u - ii;
                    ull w = (e >= 0) ? w8[e] : wprev[15 + e];
                    ffma2(acc[ii].x, fv.x, w);
                    ffma2(acc[ii].y, fv.y, w);
                }
            }
            #pragma unroll
            for (int t = 0; t < 7; t++) wprev[t] = wprev[t + 8];
            #pragma unroll
            for (int t = 7; t < 15; t++) wprev[t] = w8[t - 7];
            p += 4096;
        }
    }
    ulonglong2* Y2 = (ulonglong2*)(g_YNp + (size_t)blockIdx.y * NYN * 256);
    #pragma unroll
    for (int ii = 0; ii < 16; ii++)
        Y2[(size_t)(i0 + ii) * 64 + cp4] = acc[ii];
}

// ------------------- K7: combine 4 Y partials + cubic interp; 8 outputs/thread -------------------
__global__ void __launch_bounds__(256) k7_out(float* __restrict__ out) {
    const int idx = blockIdx.x * 256 + threadIdx.x;   // [0, 800000)
    const int i0 = idx >> 6;                          // [0, 12500)
    const int cq = idx & 63;

    const float4* Y = (const float4*)g_YNp;
    const size_t S = (size_t)NYN * 64;                // float4 per partial

    float4 n[4];
    #pragma unroll
    for (int k = 0; k < 4; k++) {
        const size_t base = (size_t)(i0 + k) * 64 + cq;
        float4 a = Y[base], b = Y[S + base], c4 = Y[2 * S + base], d = Y[3 * S + base];
        n[k].x = (a.x + b.x) + (c4.x + d.x);
        n[k].y = (a.y + b.y) + (c4.y + d.y);
        n[k].z = (a.z + b.z) + (c4.z + d.z);
        n[k].w = (a.w + b.w) + (c4.w + d.w);
    }

    float4* o4 = (float4*)out;
    #pragma unroll
    for (int j = 0; j < 8; j++) {
        const float s = (float)j * 0.125f;
        const float sm1 = s + 1.f, s1 = s - 1.f, s2 = s - 2.f;
        const float wm1 = -s * s1 * s2 * (1.f / 6.f);
        const float w0  = sm1 * s1 * s2 * 0.5f;
        const float w1  = -sm1 * s * s2 * 0.5f;
        const float w2  = sm1 * s * s1 * (1.f / 6.f);
        float4 r;
        r.x = wm1 * n[0].x + w0 * n[1].x + w1 * n[2].x + w2 * n[3].x;
        r.y = wm1 * n[0].y + w0 * n[1].y + w1 * n[2].y + w2 * n[3].y;
        r.z = wm1 * n[0].z + w0 * n[1].z + w1 * n[2].z + w2 * n[3].z;
        r.w = wm1 * n[0].w + w0 * n[1].w + w1 * n[2].w + w2 * n[3].w;
        o4[(size_t)(8 * i0 + j) * 64 + cq] = r;
    }
}

// ------------------- launch -------------------
extern "C" void kernel_launch(void* const* d_in, const int* in_sizes, int n_in,
                              void* d_out, int out_size) {
    const float* x   = (const float*)d_in[0];   // firings (1,100000,512)
    const float* gl  = (const float*)d_in[1];   // gauss_low (K taps)
    const float* gh  = (const float*)d_in[2];   // gauss_high (K taps)
    const int*   sel = (const int*)d_in[3];     // sel_idx (256)
    float* out = (float*)d_out;

    const int K   = in_sizes[1];                // 12001 (arange fp quirk)
    const int pad = (K - 1) / 2;                // TF SAME left pad

    (void)n_in; (void)out_size;

    k2_prep<<<1, 256>>>(gl, gh, K, pad);
    k3_presum<<<S8_ROWS, 256>>>(x, sel);
    k3b_mean<<<49, 256>>>(K, pad);
    k4_lownodes<<<dim3(49, NPHASE), 256>>>();
    k4c_combine<<<NLN, 256>>>();
    k5_filt<<<F_ROWS, 256>>>(x, sel);
    k6_conv<<<dim3(196, NYPART), 256>>>();
    k7_out<<<3125, 256>>>(out);
}

// round 12
// speedup vs baseline: 1.0630x; 1.0630x over previous
#include <cuda_runtime.h>
#include <cuda_bf16.h>

// FrequencyFilter: gather 256 ch -> K-tap gauss_low (sigma=2000 samp) low-pass
// -> filt = x - low + mean(low) -> K-tap gauss_high (sigma=100 samp) smoothing.
// K = 12001, pad = (K-1)//2 = 6000 (parameterized at runtime).
//
//  * low computed at stride-64 nodes from 8-sample presums (S8) with aggregated
//    8-tap avg weights (8-phase x 2-half polyphase), cubic interpolated.
//  * output computed at stride-8 nodes (8-phase polyphase over ~±4.4 sigma of
//    gauss_high, ONE phase per block for max latency hiding), cubic interp.
//  * mean(low) via prefix sums of gauss_low + channel-summed S8.
//  * conv threads own 4 channels (LDG.128 rows), packed fma.rn.f32x2 math,
//    per-phase weight tables enabling paired 128-bit weight loads.

#define T_LEN   100000
#define C_SEL   256
#define C_IN    512

// ---- low-pass stage (S8) ----
#define S8_N     12500            // 8-sample presum blocks
#define S8_PADL  768
#define S8_PADR  832
#define S8_ROWS  (S8_PADL + S8_N + S8_PADR)   // 14100
#define NLN      1568             // low nodes, node j at t = 64*(j-1)
#define NPHASE   16               // 8 phases x 2 tap-range halves

// ---- filt buffer (zero padded in time) ----
#define F_PADL   640
#define F_PADR   736
#define F_ROWS   (F_PADL + T_LEN + F_PADR)    // 101376

// ---- high-pass output nodes ----
#define NYN      12512            // node i at t = 8*i - 8 (12503 used + slack)
#define NYPART   8                // k6 phase split: one phase per block

typedef unsigned long long ull;

// ------------------- packed f32x2 helpers (sm_103a) -------------------
__device__ __forceinline__ ull pack2f(float v) {
    ull r; asm("mov.b64 %0, {%1, %1};" : "=l"(r) : "f"(v)); return r;
}
__device__ __forceinline__ void ffma2(ull& d, ull a, ull b) {
    asm("fma.rn.f32x2 %0, %1, %2, %0;" : "+l"(d) : "l"(a), "l"(b));
}

// ------------------- device scratch (static, no allocation) -------------------
__device__ __align__(16) float g_P[12002];                 // prefix of gauss_low
__device__ __align__(16) ull  g_WL[8 * 256];               // low weights  [r][v], {w,w} packed
__device__ __align__(16) ull  g_WHL[8 * 128];              // high weights [rr][c+64], {w,w} packed
__device__ float g_mean_num;                               // numerator of mean(low)
__device__ __align__(16) float g_S8[(size_t)S8_ROWS * 256];            // 14.4 MB
__device__ __align__(16) float g_LNp[(size_t)NPHASE * NLN * 256];      // 25.7 MB
__device__ __align__(16) float g_LN[NLN * 256];                        // 1.6 MB
__device__ __align__(16) float g_FILT[(size_t)F_ROWS * 256];           // 103.8 MB
__device__ __align__(16) float g_YNp[(size_t)NYPART * NYN * 256];      // 102.5 MB

// ------------------- K2: prefix of gauss_low + packed weight tables + init -------------------
__global__ void k2_prep(const float* __restrict__ gl, const float* __restrict__ gh,
                        int K, int pad) {
    __shared__ float tot[256];
    const int tid = threadIdx.x;
    const int base = tid * 48;
    float s = 0.f;
    for (int i = 0; i < 48; i++) { int k = base + i; if (k < K) s += gl[k]; }
    tot[tid] = s;
    __syncthreads();
    if (tid == 0) {
        float run = 0.f;
        for (int i = 0; i < 256; i++) { float v = tot[i]; tot[i] = run; run += v; }
        g_P[K] = run;
        g_mean_num = 0.f;
    }
    __syncthreads();
    float run = tot[tid];
    for (int i = 0; i < 48; i++) {
        int k = base + i;
        if (k < K) { g_P[k] = run; run += gl[k]; }
    }
    __syncthreads();
    // low weight table: g_WL[r*256+v] = avg of 8 gauss_low taps at block QQ = 8v+r-2,
    // taps k = 8*(QQ-750)+pad+{0..7}; zero outside QQ in [0,1500] or v >= 200.
    for (int q = tid; q < 8 * 256; q += 256) {
        int r = q >> 8, v = q & 255;
        float val = 0.f;
        int QQ = 8 * v + r - 2;
        if (v < 200 && QQ >= 0 && QQ <= 1500) {
            int lo = 8 * (QQ - 750) + pad;
            int hi = min(lo + 8, K);
            lo = max(lo, 0);
            if (hi > lo) val = 0.125f * (g_P[hi] - g_P[lo]);
        }
        g_WL[q] = pack2f(val);
    }
    // high weight table: g_WHL[rr*128 + c + 64] = gauss_high[pad + 8 + 8c + rr], c in [-64,64)
    for (int q = tid; q < 8 * 128; q += 256) {
        int rr = q >> 7, c = (q & 127) - 64;
        int k = pad + 8 + 8 * c + rr;
        float val = (k >= 0 && k < K) ? gh[k] : 0.f;
        g_WHL[q] = pack2f(val);
    }
}

// ------------------- K3: 8-sample presums (zero-padded rows) -------------------
__global__ void k3_presum(const float* __restrict__ x, const int* __restrict__ sel) {
    const int nb = blockIdx.x;               // [0, S8_ROWS)
    const int c = threadIdx.x;
    const int n = nb - S8_PADL;
    float v = 0.f;
    if (n >= 0 && n < S8_N) {
        const int ci = __ldg(&sel[c]);
        const float* xp = x + (size_t)(8 * n) * C_IN + ci;
        float a0 = xp[0] + xp[C_IN];
        float a1 = xp[2 * C_IN] + xp[3 * C_IN];
        float a2 = xp[4 * C_IN] + xp[5 * C_IN];
        float a3 = xp[6 * C_IN] + xp[7 * C_IN];
        v = (a0 + a1) + (a2 + a3);
    }
    g_S8[(size_t)nb * 256 + c] = v;
}

// ------------------- K3b: mean(low) numerator -------------------
__global__ void k3b_mean(int K, int pad) {
    const int n = blockIdx.x * 256 + threadIdx.x;
    float part = 0.f;
    if (n < S8_N) {
        const float4* row = (const float4*)(g_S8 + (size_t)(n + S8_PADL) * 256);
        float s = 0.f;
        #pragma unroll 8
        for (int i = 0; i < 64; i++) { float4 v = row[i]; s += (v.x + v.y) + (v.z + v.w); }
        float cf = 0.f;
        #pragma unroll
        for (int i = 0; i < 8; i++) {
            int m = 8 * n + i;
            cf += g_P[min(m + pad + 1, K)] - g_P[max(0, m + pad + 1 - T_LEN)];
        }
        part = s * cf * 0.125f;
    }
    #pragma unroll
    for (int o = 16; o > 0; o >>= 1) part += __shfl_down_sync(0xffffffffu, part, o);
    __shared__ float sw[8];
    if ((threadIdx.x & 31) == 0) sw[threadIdx.x >> 5] = part;
    __syncthreads();
    if (threadIdx.x == 0) {
        float s = 0.f;
        #pragma unroll
        for (int i = 0; i < 8; i++) s += sw[i];
        atomicAdd(&g_mean_num, s);
    }
}

// ------------------- K4: low-pass node values (4-channel threads, FFMA2) -------------------
// grid (49, 16): 4 node-groups per block; r = y&7 (phase), h = y>>3 (tap half).
__global__ void __launch_bounds__(256) k4_lownodes() {
    const int tid = threadIdx.x;
    const int grp = blockIdx.x * 4 + (tid >> 6);    // node group [0,196)
    const int cp4 = tid & 63;                       // 4-channel index
    const int r   = blockIdx.y & 7;
    const int h   = blockIdx.y >> 3;
    const int j0  = grp * 8;

    ulonglong2 acc[8];
    #pragma unroll
    for (int i = 0; i < 8; i++) { acc[i].x = 0ULL; acc[i].y = 0ULL; }

    const int rowoff = r + 8 * j0 + 8;              // padded row at v=0
    const ulonglong2* p = (const ulonglong2*)g_S8 + (size_t)rowoff * 64 + cp4;
    const ulonglong2* wp = (const ulonglong2*)(g_WL + r * 256);

    ull wprev[7];
    if (h == 0) {
        #pragma unroll
        for (int t = 0; t < 7; t++) wprev[t] = 0ULL;   // weights for v<0 are zero
    } else {
        #pragma unroll
        for (int t = 0; t < 7; t++) wprev[t] = g_WL[r * 256 + 89 + t];
    }
    const int vb_lo = h ? 12 : 0;
    const int vb_hi = h ? 25 : 12;
    p += vb_lo * 4096;
    for (int vb = vb_lo; vb < vb_hi; vb++) {
        ull w8[8];
        {
            const int pb = vb * 4;                  // ulonglong2 pair base = v0/2
            ulonglong2 q0 = wp[pb], q1 = wp[pb + 1], q2 = wp[pb + 2], q3 = wp[pb + 3];
            w8[0] = q0.x; w8[1] = q0.y; w8[2] = q1.x; w8[3] = q1.y;
            w8[4] = q2.x; w8[5] = q2.y; w8[6] = q3.x; w8[7] = q3.y;
        }
        #pragma unroll
        for (int u = 0; u < 8; u++) {
            ulonglong2 sv = p[u * 512];
            #pragma unroll
            for (int ii = 0; ii < 8; ii++) {
                int e = u - ii;
                ull w = (e >= 0) ? w8[e] : wprev[7 + e];
                ffma2(acc[ii].x, sv.x, w);
                ffma2(acc[ii].y, sv.y, w);
            }
        }
        #pragma unroll
        for (int t = 0; t < 7; t++) wprev[t] = w8[t + 1];
        p += 4096;
    }
    ulonglong2* out = (ulonglong2*)(g_LNp + (size_t)blockIdx.y * NLN * 256);
    #pragma unroll
    for (int ii = 0; ii < 8; ii++)
        out[(size_t)(j0 + ii) * 64 + cp4] = acc[ii];
}

// ------------------- K4c: combine 16 phase partials -------------------
__global__ void k4c_combine() {
    const size_t i = (size_t)blockIdx.x * 256 + threadIdx.x;   // NLN*256
    const size_t S = (size_t)NLN * 256;
    float s = 0.f;
    #pragma unroll
    for (int p = 0; p < NPHASE; p++) s += g_LNp[(size_t)p * S + i];
    g_LN[i] = s;
}

// ------------------- K5: materialize filt = x - interp(low) + mean (zero padded) -------------------
__global__ void k5_filt(const float* __restrict__ x, const int* __restrict__ sel) {
    const int row = blockIdx.x;            // [0, F_ROWS)
    const int m = row - F_PADL;
    const int c = threadIdx.x;
    float v = 0.f;
    if (m >= 0 && m < T_LEN) {
        const int j0 = m >> 6;
        const float s = (float)(m & 63) * (1.f / 64.f);
        const float sm1 = s + 1.f, s1 = s - 1.f, s2 = s - 2.f;
        const float wm1 = -s * s1 * s2 * (1.f / 6.f);
        const float w0  = sm1 * s1 * s2 * 0.5f;
        const float w1  = -sm1 * s * s2 * 0.5f;
        const float w2  = sm1 * s * s1 * (1.f / 6.f);
        const float* ln = g_LN + (size_t)j0 * 256 + c;
        const float lowI = wm1 * ln[0] + w0 * ln[256] + w1 * ln[512] + w2 * ln[768];
        const float mean = g_mean_num * (1.f / 25600000.f);
        v = x[(size_t)m * C_IN + __ldg(&sel[c])] - lowI + mean;
    }
    g_FILT[(size_t)row * 256 + c] = v;
}

// ------------------- K6: high-pass conv at stride-8 nodes (one phase/block, FFMA2) ----
// Node i at t = 8i - 8. Y[i] = sum_k wh[k] * filt[t + k - pad].
// Tap offsets c in [-55,55] (~±4.4 sigma). Phase rr = blockIdx.y (8-way split
// into partial buffers; per-thread work halved vs 4-way for latency hiding).
__global__ void __launch_bounds__(256) k6_conv() {
    const int tid = threadIdx.x;
    const int grp = blockIdx.x * 4 + (tid >> 6);    // node group [0,1564)
    const int cp4 = tid & 63;                       // 4-channel index
    const int i0  = grp * 8;
    const int rr  = blockIdx.y;                     // phase [0,8)

    ulonglong2 acc[8];
    #pragma unroll
    for (int i = 0; i < 8; i++) { acc[i].x = 0ULL; acc[i].y = 0ULL; }

    const ulonglong2* p = (const ulonglong2*)g_FILT
                        + (size_t)(8 * i0 + rr + F_PADL) * 64 + cp4
                        - 48 * 512;                  // position at cb = -48
    const ulonglong2* wp = (const ulonglong2*)(g_WHL + rr * 128);
    ull wprev[7];
    #pragma unroll
    for (int t = 0; t < 7; t++) wprev[t] = g_WHL[rr * 128 + 9 + t];  // c = -55..-49
    for (int cb = -48; cb <= 48; cb += 8) {
        ull w8[8];
        {
            const int pb = (cb + 64) >> 1;           // ulonglong2 pair base
            ulonglong2 q0 = wp[pb], q1 = wp[pb + 1], q2 = wp[pb + 2], q3 = wp[pb + 3];
            w8[0] = q0.x; w8[1] = q0.y; w8[2] = q1.x; w8[3] = q1.y;
            w8[4] = q2.x; w8[5] = q2.y; w8[6] = q3.x; w8[7] = q3.y;
        }
        #pragma unroll
        for (int u = 0; u < 8; u++) {
            ulonglong2 fv = p[u * 512];
            #pragma unroll
            for (int ii = 0; ii < 8; ii++) {
                int e = u - ii;
                ull w = (e >= 0) ? w8[e] : wprev[7 + e];
                ffma2(acc[ii].x, fv.x, w);
                ffma2(acc[ii].y, fv.y, w);
            }
        }
        #pragma unroll
        for (int t = 0; t < 7; t++) wprev[t] = w8[t + 1];
        p += 4096;
    }
    ulonglong2* Y2 = (ulonglong2*)(g_YNp + (size_t)blockIdx.y * NYN * 256);
    #pragma unroll
    for (int ii = 0; ii < 8; ii++)
        Y2[(size_t)(i0 + ii) * 64 + cp4] = acc[ii];
}

// ------------------- K7: combine 8 Y partials + cubic interp; 8 outputs/thread -------------------
__global__ void __launch_bounds__(256) k7_out(float* __restrict__ out) {
    const int idx = blockIdx.x * 256 + threadIdx.x;   // [0, 800000)
    const int i0 = idx >> 6;                          // [0, 12500)
    const int cq = idx & 63;

    const float4* Y = (const float4*)g_YNp;
    const size_t S = (size_t)NYN * 64;                // float4 per partial

    float4 n[4];
    #pragma unroll
    for (int k = 0; k < 4; k++) {
        const size_t base = (size_t)(i0 + k) * 64 + cq;
        float4 a = Y[base];
        #pragma unroll
        for (int pp = 1; pp < NYPART; pp++) {
            float4 b = Y[(size_t)pp * S + base];
            a.x += b.x; a.y += b.y; a.z += b.z; a.w += b.w;
        }
        n[k] = a;
    }

    float4* o4 = (float4*)out;
    #pragma unroll
    for (int j = 0; j < 8; j++) {
        const float s = (float)j * 0.125f;
        const float sm1 = s + 1.f, s1 = s - 1.f, s2 = s - 2.f;
        const float wm1 = -s * s1 * s2 * (1.f / 6.f);
        const float w0  = sm1 * s1 * s2 * 0.5f;
        const float w1  = -sm1 * s * s2 * 0.5f;
        const float w2  = sm1 * s * s1 * (1.f / 6.f);
        float4 r;
        r.x = wm1 * n[0].x + w0 * n[1].x + w1 * n[2].x + w2 * n[3].x;
        r.y = wm1 * n[0].y + w0 * n[1].y + w1 * n[2].y + w2 * n[3].y;
        r.z = wm1 * n[0].z + w0 * n[1].z + w1 * n[2].z + w2 * n[3].z;
        r.w = wm1 * n[0].w + w0 * n[1].w + w1 * n[2].w + w2 * n[3].w;
        o4[(size_t)(8 * i0 + j) * 64 + cq] = r;
    }
}

// ------------------- launch -------------------
extern "C" void kernel_launch(void* const* d_in, const int* in_sizes, int n_in,
                              void* d_out, int out_size) {
    const float* x   = (const float*)d_in[0];   // firings (1,100000,512)
    const float* gl  = (const float*)d_in[1];   // gauss_low (K taps)
    const float* gh  = (const float*)d_in[2];   // gauss_high (K taps)
    const int*   sel = (const int*)d_in[3];     // sel_idx (256)
    float* out = (float*)d_out;

    const int K   = in_sizes[1];                // 12001 (arange fp quirk)
    const int pad = (K - 1) / 2;                // TF SAME left pad

    (void)n_in; (void)out_size;

    k2_prep<<<1, 256>>>(gl, gh, K, pad);
    k3_presum<<<S8_ROWS, 256>>>(x, sel);
    k3b_mean<<<49, 256>>>(K, pad);
    k4_lownodes<<<dim3(49, NPHASE), 256>>>();
    k4c_combine<<<NLN, 256>>>();
    k5_filt<<<F_ROWS, 256>>>(x, sel);
    k6_conv<<<dim3(391, NYPART), 256>>>();
    k7_out<<<3125, 256>>>(out);
}